// round 13
// baseline (speedup 1.0000x reference)
#include <cuda_runtime.h>
#include <cstdint>
#include <math.h>

#define Bb 16
#define Ff 128
#define Nn 2048
#define BN (Bb*Nn)          // 32768
#define TOT (Bb*Ff*Nn)      // 4194304
#define NBLK 512            // k_fused grid size

// scratch (allocation-free: __device__ globals)
__device__ float g_s[BN];
__device__ float g_E[BN];
__device__ float g_psum[NBLK];
__device__ float g_psq[NBLK];

// ---------------------------------------------------------------------------
// Pass 1: s[b,n] = sum_f v[f]*emb[b,f,n]; per-block partial sum/sumsq.
// Proven-fastest structure (R7, 7.2us): 512 thr = 8 fc (16 f) x 64 n. Grid 512.
// ---------------------------------------------------------------------------
__global__ void __launch_bounds__(512) k_fused(const float* __restrict__ emb,
                                               const float* __restrict__ v) {
    __shared__ float sv[Ff];
    __shared__ float spart[512];
    __shared__ float red_sum[16];
    __shared__ float red_sq[16];

    int tid = threadIdx.x;
    if (tid < Ff) sv[tid] = v[tid];
    __syncthreads();

    int b  = blockIdx.x >> 5;          // 0..15
    int ng = blockIdx.x & 31;          // 0..31 (group of 64 n)
    int nl = tid & 63;                 // 0..63
    int fc = tid >> 6;                 // 0..7  (f-chunk of 16)
    int n  = ng * 64 + nl;

    const float* p  = emb + ((size_t)(b * Ff + fc * 16)) * Nn + n;
    const float* pv = sv + fc * 16;

    float s = 0.f, sum = 0.f, sq = 0.f;
#pragma unroll
    for (int f = 0; f < 16; f++) {
        float x = __ldg(p + (size_t)f * Nn);
        s   = fmaf(pv[f], x, s);
        sum += x;
        sq  = fmaf(x, x, sq);
    }
    spart[tid] = s;
    __syncthreads();
    if (tid < 64) {
        float tot = 0.f;
#pragma unroll
        for (int c = 0; c < 8; c++) tot += spart[c * 64 + tid];
        g_s[b * Nn + ng * 64 + tid] = tot;
    }

    // block reduce sum & sq -> plain per-block stores
    int lane = tid & 31;
    int wid  = tid >> 5;
#pragma unroll
    for (int o = 16; o > 0; o >>= 1) {
        sum += __shfl_xor_sync(0xffffffffu, sum, o);
        sq  += __shfl_xor_sync(0xffffffffu, sq, o);
    }
    if (lane == 0) { red_sum[wid] = sum; red_sq[wid] = sq; }
    __syncthreads();
    if (wid == 0) {
        float rs = (lane < 16) ? red_sum[lane] : 0.f;
        float rq = (lane < 16) ? red_sq[lane]  : 0.f;
#pragma unroll
        for (int o = 8; o > 0; o >>= 1) {
            rs += __shfl_xor_sync(0xffffffffu, rs, o);
            rq += __shfl_xor_sync(0xffffffffu, rq, o);
        }
        if (lane == 0) {
            g_psum[blockIdx.x] = rs;
            g_psq[blockIdx.x]  = rq;
        }
    }
}

// ---------------------------------------------------------------------------
// Pass 2: 64 blocks x 512 thr. Each block redundantly reduces the 512
// L2-resident partials -> scale, then E[n] = exp(-(s[n]*scale + bias/2)).
// ---------------------------------------------------------------------------
__global__ void __launch_bounds__(512) k_exp(const float* __restrict__ bias) {
    __shared__ float red_sum[16];
    __shared__ float red_sq[16];
    __shared__ float sh_scale, sh_hb;

    int tid  = threadIdx.x;
    int lane = tid & 31;
    int wid  = tid >> 5;

    float sum = g_psum[tid];
    float sq  = g_psq[tid];
#pragma unroll
    for (int o = 16; o > 0; o >>= 1) {
        sum += __shfl_xor_sync(0xffffffffu, sum, o);
        sq  += __shfl_xor_sync(0xffffffffu, sq, o);
    }
    if (lane == 0) { red_sum[wid] = sum; red_sq[wid] = sq; }
    __syncthreads();
    if (tid == 0) {
        double ds = 0.0, dq = 0.0;
#pragma unroll
        for (int w = 0; w < 16; w++) { ds += (double)red_sum[w]; dq += (double)red_sq[w]; }
        double m   = (double)TOT;
        double var = (dq - ds * ds / m) / (m - 1.0);
        sh_scale = (float)(1.0 / sqrt(var));
        sh_hb    = 0.5f * bias[0];
    }
    __syncthreads();

    int idx = blockIdx.x * 512 + tid;   // 64 * 512 = 32768 = BN
    float t = fmaf(g_s[idx], sh_scale, sh_hb);
    g_E[idx] = __expf(-t);
}

// ---------------------------------------------------------------------------
// Pass 3: out[b,i,j] = 1/(1 + E_i*E_j). 8 rows per block (halved per-block
// overhead + halved E_j L2 traffic vs 4-row), row-wise compute keeps regs low.
// Plain float4 stores (proven fastest).
// ---------------------------------------------------------------------------
__device__ __forceinline__ float frcp(float x) {
    float r;
    asm("rcp.approx.f32 %0, %1;" : "=f"(r) : "f"(x));
    return r;
}

__global__ void __launch_bounds__(512) k_main(float* __restrict__ out) {
    __shared__ float sh_p[8];

    int tid = threadIdx.x;
    int r0  = blockIdx.x << 3;         // first of 8 rows
    int b   = r0 >> 11;

    if (tid < 8) sh_p[tid] = __ldg(g_E + r0 + tid);
    __syncthreads();

    float4 ej = __ldg((const float4*)(g_E + (size_t)b * Nn) + tid);
    float4* orow = (float4*)(out + (size_t)r0 * Nn) + tid;

#pragma unroll
    for (int r = 0; r < 8; r++) {
        float p = sh_p[r];
        float4 o;
        o.x = frcp(fmaf(p, ej.x, 1.f));
        o.y = frcp(fmaf(p, ej.y, 1.f));
        o.z = frcp(fmaf(p, ej.z, 1.f));
        o.w = frcp(fmaf(p, ej.w, 1.f));
        orow[(size_t)r * (Nn / 4)] = o;
    }
}

extern "C" void kernel_launch(void* const* d_in, const int* in_sizes, int n_in,
                              void* d_out, int out_size) {
    // inputs: adj_in [B,N,N] (unused), emb_in [B,F,N], v [F], b [1]
    const float* emb  = (const float*)d_in[1];
    const float* v    = (const float*)d_in[2];
    const float* bias = (const float*)d_in[3];
    float* out = (float*)d_out;

    k_fused<<<NBLK, 512>>>(emb, v);
    k_exp<<<BN / 512, 512>>>(bias);
    k_main<<<BN / 8, 512>>>(out);
}